// round 12
// baseline (speedup 1.0000x reference)
#include <cuda_runtime.h>
#include <cstdint>

#define BB 64
#define NN 512
#define FF 64
#define HH 128
#define RR (BB*NN)   /* 32768 rows */
#define INV_T 100.0f

typedef unsigned long long u64;

// ---------------- scratch (device globals: allowed, no allocation) ----------
__device__ float g_h[RR*HH];     // 16.8 MB
__device__ float g_m[RR*HH];     // 16.8 MB
__device__ float g_agg[RR*HH];   // 16.8 MB
__device__ float g_s[RR*3];      // 0.4 MB

__device__ __forceinline__ float sig_(float x)  { return 1.f/(1.f+__expf(-x)); }
__device__ __forceinline__ float tanh_(float x) { return 2.f/(1.f+__expf(-2.f*x)) - 1.f; }

// ---- packed fp32x2 FMA helpers (FFMA2: ptxas never emits from C++) ---------
__device__ __forceinline__ u64 pack2_(float a) {
    u64 r; asm("mov.b64 %0, {%1, %1};" : "=l"(r) : "r"(__float_as_uint(a)));
    return r;
}
__device__ __forceinline__ void ffma2_(u64& d, u64 a, u64 b) {
    asm("fma.rn.f32x2 %0, %1, %2, %0;" : "+l"(d) : "l"(a), "l"(b));
}
__device__ __forceinline__ float2 unpack2_(u64 v) {
    unsigned lo, hi;
    asm("mov.b64 {%0, %1}, %2;" : "=r"(lo), "=r"(hi) : "l"(v));
    return make_float2(__uint_as_float(lo), __uint_as_float(hi));
}

// 4-row x 4-col panel accumulate: acc += A(smem rows m0..m0+3) * W(gmem, L2-hot)
__device__ __forceinline__ void panel_acc4(
    const float* __restrict__ Wg, const float* sA,
    int m0, int c0, u64* acc01, u64* acc23)
{
    #pragma unroll 2
    for (int k = 0; k < HH; k += 2) {
        ulonglong2 w0 = __ldg((const ulonglong2*)(Wg + (size_t)(k  )*HH + c0));
        ulonglong2 w1 = __ldg((const ulonglong2*)(Wg + (size_t)(k+1)*HH + c0));
        #pragma unroll
        for (int i=0;i<4;i++) {
            float2 a = *(const float2*)(sA + (m0+i)*HH + k);
            u64 a0 = pack2_(a.x), a1 = pack2_(a.y);
            ffma2_(acc01[i], a0, w0.x); ffma2_(acc23[i], a0, w0.y);
            ffma2_(acc01[i], a1, w1.x); ffma2_(acc23[i], a1, w1.y);
        }
    }
}

// ---------------- K1: h = relu(x@W_emb + b) + pos ; also init s -------------
__global__ void __launch_bounds__(256, 2) k_embed(
    const float* __restrict__ x, const float* __restrict__ W,
    const float* __restrict__ bias, const float* __restrict__ pos)
{
    extern __shared__ float sm[];
    float* Xs = sm;             // [64][64]
    float* Ws = sm + 64*FF;     // [64][128]
    int tid = threadIdx.x;
    int row0 = blockIdx.x * 64;

    {   // tile loads (contiguous)
        const float4* xg = (const float4*)(x + (size_t)row0*FF);
        float4* Xs4 = (float4*)Xs;
        #pragma unroll
        for (int i = tid; i < 64*FF/4; i += 256) Xs4[i] = xg[i];
        const float4* wg = (const float4*)W;
        float4* Ws4 = (float4*)Ws;
        #pragma unroll
        for (int i = tid; i < FF*HH/4; i += 256) Ws4[i] = wg[i];
    }
    if (tid < 64) {  // init spatial variable s
        int r = row0 + tid;
        int n = r & (NN-1);
        g_s[r*3+0] = ((float)n - (NN-1)*0.5f) / (float)NN;
        g_s[r*3+1] = 0.f;
        g_s[r*3+2] = 0.f;
    }
    __syncthreads();

    int tx = tid & 31, ty = tid >> 5;
    int c0 = tx*4, m0 = ty*8;
    u64 acc01[8], acc23[8];
    #pragma unroll
    for (int i=0;i<8;i++){ acc01[i]=0ull; acc23[i]=0ull; }

    #pragma unroll 2
    for (int k = 0; k < FF; k += 2) {
        ulonglong2 w0 = *(const ulonglong2*)(Ws + (k  )*HH + c0);
        ulonglong2 w1 = *(const ulonglong2*)(Ws + (k+1)*HH + c0);
        #pragma unroll
        for (int i=0;i<8;i++) {
            float2 a = *(const float2*)(Xs + (m0+i)*FF + k);
            u64 a0 = pack2_(a.x), a1 = pack2_(a.y);
            ffma2_(acc01[i], a0, w0.x); ffma2_(acc23[i], a0, w0.y);
            ffma2_(acc01[i], a1, w1.x); ffma2_(acc23[i], a1, w1.y);
        }
    }
    float4 bb = *(const float4*)(bias + c0);
    #pragma unroll
    for (int i=0;i<8;i++) {
        int r = row0 + m0 + i;
        int n = r & (NN-1);
        float4 p = *(const float4*)(pos + (size_t)n*HH + c0);
        float2 v01 = unpack2_(acc01[i]);
        float2 v23 = unpack2_(acc23[i]);
        float4 o;
        o.x = fmaxf(v01.x+bb.x, 0.f) + p.x;
        o.y = fmaxf(v01.y+bb.y, 0.f) + p.y;
        o.z = fmaxf(v23.x+bb.z, 0.f) + p.z;
        o.w = fmaxf(v23.y+bb.w, 0.f) + p.w;
        *(float4*)(g_h + (size_t)r*HH + c0) = o;
    }
}

// ---------------- K2: m = relu(h @ Wm[i] + bm[i])  (32-row tiles) -----------
__global__ void __launch_bounds__(256, 4) k_msg(
    const float* __restrict__ Wm, const float* __restrict__ bm, int iter)
{
    __shared__ float Hs[32*HH];        // 16 KB
    const float* W  = Wm + (size_t)iter*HH*HH;
    const float* bv = bm + (size_t)iter*HH;
    int tid = threadIdx.x;
    int row0 = blockIdx.x * 32;

    {
        const float4* hg = (const float4*)(g_h + (size_t)row0*HH);
        float4* Hs4 = (float4*)Hs;
        #pragma unroll
        for (int i = tid; i < 32*HH/4; i += 256) Hs4[i] = hg[i];
    }
    __syncthreads();

    int tx = tid & 31, wid = tid >> 5;
    int c0 = tx*4, m0 = wid*4;
    u64 acc01[4], acc23[4];
    #pragma unroll
    for (int i=0;i<4;i++){ acc01[i]=0ull; acc23[i]=0ull; }

    panel_acc4(W, Hs, m0, c0, acc01, acc23);

    float4 bb = __ldg((const float4*)(bv + c0));
    #pragma unroll
    for (int i=0;i<4;i++) {
        int r = row0 + m0 + i;
        float2 v01 = unpack2_(acc01[i]);
        float2 v23 = unpack2_(acc23[i]);
        float4 o;
        o.x = fmaxf(v01.x+bb.x, 0.f);
        o.y = fmaxf(v01.y+bb.y, 0.f);
        o.z = fmaxf(v23.x+bb.z, 0.f);
        o.w = fmaxf(v23.y+bb.w, 0.f);
        *(float4*)(g_m + (size_t)r*HH + c0) = o;
    }
}

// ---------------- K3: agg = A(s) @ m   (A computed on the fly) --------------
__global__ void __launch_bounds__(256, 2) k_agg(const float* __restrict__ mask)
{
    extern __shared__ float sm[];
    float* s0 = sm;
    float* s1 = sm + 512;
    float* s2 = sm + 1024;
    float* sq = sm + 1536;
    float* As = sm + 2048;              // [64][64]
    float* Ms = sm + 2048 + 64*64;      // [64][128]
    int tid = threadIdx.x;
    int b = blockIdx.x >> 3;
    int itile = blockIdx.x & 7;
    int i0 = itile * 64;                // local row start inside batch

    for (int j = tid; j < NN; j += 256) {
        float a0 = g_s[((size_t)b*NN + j)*3 + 0];
        float a1 = g_s[((size_t)b*NN + j)*3 + 1];
        float a2 = g_s[((size_t)b*NN + j)*3 + 2];
        s0[j]=a0; s1[j]=a1; s2[j]=a2;
        sq[j] = a0*a0 + a1*a1 + a2*a2;
    }
    __syncthreads();

    int tx = tid & 31, ty = tid >> 5;
    int c0 = tx*4, m0 = ty*8;
    u64 acc01[8], acc23[8];
    #pragma unroll
    for (int i=0;i<8;i++){ acc01[i]=0ull; acc23[i]=0ull; }

    const float* maskb = mask + (size_t)b*NN*NN;

    for (int jt = 0; jt < 8; jt++) {
        int j0 = jt * 64;
        // stage m tile
        {
            const float4* mg = (const float4*)(g_m + ((size_t)b*NN + j0)*HH);
            float4* Ms4 = (float4*)Ms;
            #pragma unroll
            for (int i2 = tid; i2 < 64*HH/4; i2 += 256) Ms4[i2] = mg[i2];
        }
        // compute A tile (mask reads coalesced over j)
        #pragma unroll
        for (int p = tid; p < 64*64; p += 256) {
            int jl = p & 63, il = p >> 6;
            int gi = i0 + il, gj = j0 + jl;
            float d2 = sq[gi] + sq[gj]
                     - 2.f*(s0[gi]*s0[gj] + s1[gi]*s1[gj] + s2[gi]*s2[gj]);
            float mv = __ldg(maskb + (size_t)gi*NN + gj);
            As[il*64 + jl] = __expf(-d2*INV_T) * mv;
        }
        __syncthreads();
        #pragma unroll 2
        for (int k = 0; k < 64; k += 2) {
            ulonglong2 w0 = *(const ulonglong2*)(Ms + (k  )*HH + c0);
            ulonglong2 w1 = *(const ulonglong2*)(Ms + (k+1)*HH + c0);
            #pragma unroll
            for (int i=0;i<8;i++) {
                float2 a = *(const float2*)(As + (m0+i)*64 + k);
                u64 a0 = pack2_(a.x), a1 = pack2_(a.y);
                ffma2_(acc01[i], a0, w0.x); ffma2_(acc23[i], a0, w0.y);
                ffma2_(acc01[i], a1, w1.x); ffma2_(acc23[i], a1, w1.y);
            }
        }
        __syncthreads();
    }
    int rbase = b*NN + i0;
    #pragma unroll
    for (int i=0;i<8;i++) {
        float2 v01 = unpack2_(acc01[i]);
        float2 v23 = unpack2_(acc23[i]);
        float4 o; o.x=v01.x; o.y=v01.y; o.z=v23.x; o.w=v23.y;
        *(float4*)(g_agg + (size_t)(rbase+m0+i)*HH + c0) = o;
    }
}

// -------- K4: fused GRU vertex update + positional GRU (32-row tiles) -------
__global__ void __launch_bounds__(256, 3) k_gru(
    const float* __restrict__ Wz_, const float* __restrict__ Uz_, const float* __restrict__ bz_,
    const float* __restrict__ Wr_, const float* __restrict__ Ur_, const float* __restrict__ br_,
    const float* __restrict__ Wh_, const float* __restrict__ Uh_, const float* __restrict__ bh_,
    const float* __restrict__ Wpz, const float* __restrict__ Upz, const float* __restrict__ bpz,
    const float* __restrict__ Wpr, const float* __restrict__ Upr, const float* __restrict__ bpr,
    const float* __restrict__ Wph, const float* __restrict__ Uph, const float* __restrict__ bph,
    int iter)
{
    __shared__ float aggs[32*HH];   // 16 KB; becomes h_new after hh panel
    __shared__ float hs  [32*HH];   // 16 KB
    __shared__ float rh  [32*HH];   // 16 KB (r*h)
    __shared__ float srs [32*3];

    const float* Wz = Wz_ + (size_t)iter*HH*HH;
    const float* Uz = Uz_ + (size_t)iter*HH*HH;
    const float* Wr = Wr_ + (size_t)iter*HH*HH;
    const float* Ur = Ur_ + (size_t)iter*HH*HH;
    const float* Wh = Wh_ + (size_t)iter*HH*HH;
    const float* Uh = Uh_ + (size_t)iter*HH*HH;
    const float* bz = bz_ + (size_t)iter*HH;
    const float* br = br_ + (size_t)iter*HH;
    const float* bh = bh_ + (size_t)iter*HH;

    int tid = threadIdx.x;
    int row0 = blockIdx.x * 32;

    {
        const float4* ag = (const float4*)(g_agg + (size_t)row0*HH);
        const float4* hg = (const float4*)(g_h  + (size_t)row0*HH);
        float4* a4 = (float4*)aggs; float4* h4 = (float4*)hs;
        #pragma unroll
        for (int i = tid; i < 32*HH/4; i += 256) { a4[i] = ag[i]; h4[i] = hg[i]; }
    }
    __syncthreads();

    int tx = tid & 31, wid = tid >> 5;
    int c0 = tx*4, m0 = wid*4;

    // ---- z panel ----
    float z[4][4];
    {
        u64 acc01[4], acc23[4];
        #pragma unroll
        for (int i=0;i<4;i++){ acc01[i]=0ull; acc23[i]=0ull; }
        panel_acc4(Wz, aggs, m0, c0, acc01, acc23);
        panel_acc4(Uz, hs,   m0, c0, acc01, acc23);
        float4 bb = __ldg((const float4*)(bz + c0));
        #pragma unroll
        for (int i=0;i<4;i++) {
            float2 v01 = unpack2_(acc01[i]);
            float2 v23 = unpack2_(acc23[i]);
            z[i][0]=sig_(v01.x+bb.x); z[i][1]=sig_(v01.y+bb.y);
            z[i][2]=sig_(v23.x+bb.z); z[i][3]=sig_(v23.y+bb.w);
        }
    }
    // ---- r panel -> rh = r*h (rows are warp-private: syncwarp suffices) ----
    {
        u64 acc01[4], acc23[4];
        #pragma unroll
        for (int i=0;i<4;i++){ acc01[i]=0ull; acc23[i]=0ull; }
        panel_acc4(Wr, aggs, m0, c0, acc01, acc23);
        panel_acc4(Ur, hs,   m0, c0, acc01, acc23);
        float4 bb = __ldg((const float4*)(br + c0));
        #pragma unroll
        for (int i=0;i<4;i++) {
            float2 v01 = unpack2_(acc01[i]);
            float2 v23 = unpack2_(acc23[i]);
            float rr[4];
            rr[0]=sig_(v01.x+bb.x); rr[1]=sig_(v01.y+bb.y);
            rr[2]=sig_(v23.x+bb.z); rr[3]=sig_(v23.y+bb.w);
            #pragma unroll
            for (int j=0;j<4;j++)
                rh[(m0+i)*HH + c0 + j] = rr[j] * hs[(m0+i)*HH + c0 + j];
        }
    }
    __syncwarp();
    // ---- hh panel + h update; write h_new into aggs (dead after Wh loop) ---
    {
        u64 acc01[4], acc23[4];
        #pragma unroll
        for (int i=0;i<4;i++){ acc01[i]=0ull; acc23[i]=0ull; }
        panel_acc4(Wh, aggs, m0, c0, acc01, acc23);
        panel_acc4(Uh, rh,   m0, c0, acc01, acc23);
        float4 bb = __ldg((const float4*)(bh + c0));
        float hn[4][4];
        #pragma unroll
        for (int i=0;i<4;i++) {
            float2 v01 = unpack2_(acc01[i]);
            float2 v23 = unpack2_(acc23[i]);
            float pre[4] = {v01.x+bb.x, v01.y+bb.y, v23.x+bb.z, v23.y+bb.w};
            #pragma unroll
            for (int j=0;j<4;j++) {
                float hhv = tanh_(pre[j]);
                float hv  = hs[(m0+i)*HH + c0 + j];
                hn[i][j] = (1.f - z[i][j])*hv + z[i][j]*hhv;
            }
            float4 o; o.x=hn[i][0]; o.y=hn[i][1]; o.z=hn[i][2]; o.w=hn[i][3];
            *(float4*)(g_h + (size_t)(row0+m0+i)*HH + c0) = o;
        }
        __syncwarp();              // warp done reading its aggs rows
        #pragma unroll
        for (int i=0;i<4;i++) {    // aggs now holds h_new
            float4 o; o.x=hn[i][0]; o.y=hn[i][1]; o.z=hn[i][2]; o.w=hn[i][3];
            *(float4*)(aggs + (m0+i)*HH + c0) = o;
        }
    }
    __syncthreads();

    // ---- positional GRU (3-dim state), 3 threads per row; h_new in aggs ----
    int m = tid / 3, d = tid - m*3;
    int r = row0 + m;
    float sv0=0.f, sv1=0.f, sv2=0.f, ah=0.f, zs=0.f;
    if (tid < 96) {
        sv0 = g_s[(size_t)r*3+0]; sv1 = g_s[(size_t)r*3+1]; sv2 = g_s[(size_t)r*3+2];
        float az=0.f, ar=0.f; ah=0.f;
        #pragma unroll 4
        for (int k = 0; k < HH; k++) {
            float hv = aggs[m*HH + k];
            az += hv * __ldg(Wpz + k*3 + d);
            ar += hv * __ldg(Wpr + k*3 + d);
            ah += hv * __ldg(Wph + k*3 + d);
        }
        float zu = sv0*__ldg(Upz+0+d) + sv1*__ldg(Upz+3+d) + sv2*__ldg(Upz+6+d);
        float ru = sv0*__ldg(Upr+0+d) + sv1*__ldg(Upr+3+d) + sv2*__ldg(Upr+6+d);
        zs = sig_(az + zu + __ldg(bpz + d));
        float rsv = sig_(ar + ru + __ldg(bpr + d));
        srs[m*3 + d] = rsv;
    }
    __syncthreads();
    if (tid < 96) {
        float hu = srs[m*3+0]*sv0*__ldg(Uph+0+d)
                 + srs[m*3+1]*sv1*__ldg(Uph+3+d)
                 + srs[m*3+2]*sv2*__ldg(Uph+6+d);
        float ssv = tanh_(ah + hu + __ldg(bph + d));
        float sd = (d==0) ? sv0 : (d==1) ? sv1 : sv2;
        g_s[(size_t)r*3 + d] = (1.f - zs)*sd + zs*ssv;
    }
}

// ---------------- K5: final A = exp(-d2/T) * mask ---------------------------
__global__ void k_final(const float* __restrict__ mask, float* __restrict__ out)
{
    __shared__ float s0[512], s1[512], s2[512], sq[512];
    int tid = threadIdx.x;
    int b = blockIdx.x >> 3;
    int itile = blockIdx.x & 7;
    int i0 = itile * 64;

    for (int j = tid; j < NN; j += 256) {
        float a0 = g_s[((size_t)b*NN + j)*3 + 0];
        float a1 = g_s[((size_t)b*NN + j)*3 + 1];
        float a2 = g_s[((size_t)b*NN + j)*3 + 2];
        s0[j]=a0; s1[j]=a1; s2[j]=a2;
        sq[j] = a0*a0 + a1*a1 + a2*a2;
    }
    __syncthreads();

    const float* maskb = mask + (size_t)b*NN*NN;
    float* outb = out + (size_t)b*NN*NN;
    #pragma unroll 4
    for (int p = tid; p < 64*NN; p += 256) {
        int j  = p & (NN-1);
        int il = p >> 9;
        int gi = i0 + il;
        float d2 = sq[gi] + sq[j]
                 - 2.f*(s0[gi]*s0[j] + s1[gi]*s1[j] + s2[gi]*s2[j]);
        outb[(size_t)gi*NN + j] = __expf(-d2*INV_T) * __ldg(maskb + (size_t)gi*NN + j);
    }
}

// ---------------- launch -----------------------------------------------------
extern "C" void kernel_launch(void* const* d_in, const int* in_sizes, int n_in,
                              void* d_out, int out_size)
{
    (void)in_sizes; (void)n_in; (void)out_size;
    const float* x     = (const float*)d_in[0];
    const float* mask  = (const float*)d_in[1];
    const float* W_emb = (const float*)d_in[2];
    const float* b_emb = (const float*)d_in[3];
    const float* pos   = (const float*)d_in[4];
    const float* Wm    = (const float*)d_in[5];
    const float* bm    = (const float*)d_in[6];
    const float* Wz    = (const float*)d_in[7];
    const float* Uz    = (const float*)d_in[8];
    const float* bz    = (const float*)d_in[9];
    const float* Wr    = (const float*)d_in[10];
    const float* Ur    = (const float*)d_in[11];
    const float* br    = (const float*)d_in[12];
    const float* Wh    = (const float*)d_in[13];
    const float* Uh    = (const float*)d_in[14];
    const float* bh    = (const float*)d_in[15];
    const float* Wpz   = (const float*)d_in[16];
    const float* Upz   = (const float*)d_in[17];
    const float* bpz   = (const float*)d_in[18];
    const float* Wpr   = (const float*)d_in[19];
    const float* Upr   = (const float*)d_in[20];
    const float* bpr   = (const float*)d_in[21];
    const float* Wph   = (const float*)d_in[22];
    const float* Uph   = (const float*)d_in[23];
    const float* bph   = (const float*)d_in[24];
    float* out = (float*)d_out;

    const int smem_embed = (64*FF + FF*HH) * 4;                  // 48 KB
    const int smem_agg   = (4*512 + 64*64 + 64*HH) * 4;          // 56 KB

    cudaFuncSetAttribute(k_embed, cudaFuncAttributeMaxDynamicSharedMemorySize, smem_embed);
    cudaFuncSetAttribute(k_agg,   cudaFuncAttributeMaxDynamicSharedMemorySize, smem_agg);

    k_embed<<<RR/64, 256, smem_embed>>>(x, W_emb, b_emb, pos);
    for (int it = 0; it < 3; it++) {
        k_msg<<<RR/32, 256>>>(Wm, bm, it);
        k_agg<<<BB*8, 256, smem_agg>>>(mask);
        k_gru<<<RR/32, 256>>>(Wz,Uz,bz, Wr,Ur,br, Wh,Uh,bh,
                              Wpz,Upz,bpz, Wpr,Upr,bpr, Wph,Uph,bph, it);
    }
    k_final<<<BB*8, 256>>>(mask, out);
}

// round 17
// speedup vs baseline: 1.1584x; 1.1584x over previous
#include <cuda_runtime.h>
#include <cstdint>

#define BB 64
#define NN 512
#define FF 64
#define HH 128
#define RR (BB*NN)   /* 32768 rows */
#define INV_T 100.0f

typedef unsigned long long u64;

// ---------------- scratch (device globals: allowed, no allocation) ----------
__device__ float g_h[RR*HH];     // 16.8 MB
__device__ float g_m[RR*HH];     // 16.8 MB
__device__ float g_agg[RR*HH];   // 16.8 MB
__device__ float g_s[RR*3];      // 0.4 MB

__device__ __forceinline__ float sig_(float x)  { return 1.f/(1.f+__expf(-x)); }
__device__ __forceinline__ float tanh_(float x) { return 2.f/(1.f+__expf(-2.f*x)) - 1.f; }

// ---- packed fp32x2 FMA helpers (FFMA2: ptxas never emits from C++) ---------
__device__ __forceinline__ u64 pack2_(float a) {
    u64 r; asm("mov.b64 %0, {%1, %1};" : "=l"(r) : "r"(__float_as_uint(a)));
    return r;
}
__device__ __forceinline__ void ffma2_(u64& d, u64 a, u64 b) {
    asm("fma.rn.f32x2 %0, %1, %2, %0;" : "+l"(d) : "l"(a), "l"(b));
}
__device__ __forceinline__ float2 unpack2_(u64 v) {
    unsigned lo, hi;
    asm("mov.b64 {%0, %1}, %2;" : "=r"(lo), "=r"(hi) : "l"(v));
    return make_float2(__uint_as_float(lo), __uint_as_float(hi));
}

// 8-row x 4-col dual-panel accumulate: acc += sA·W + sB·U  (fused k-loop,
// 8 independent weight LDGs in flight; A reads are float4 smem broadcasts)
__device__ __forceinline__ void dual_acc8(
    const float* __restrict__ Wg, const float* __restrict__ Ug,
    const float* sA, const float* sB,
    int m0, int c0, u64* acc01, u64* acc23)
{
    #pragma unroll 1
    for (int k = 0; k < HH; k += 4) {
        ulonglong2 w0 = __ldg((const ulonglong2*)(Wg + (size_t)(k  )*HH + c0));
        ulonglong2 w1 = __ldg((const ulonglong2*)(Wg + (size_t)(k+1)*HH + c0));
        ulonglong2 w2 = __ldg((const ulonglong2*)(Wg + (size_t)(k+2)*HH + c0));
        ulonglong2 w3 = __ldg((const ulonglong2*)(Wg + (size_t)(k+3)*HH + c0));
        ulonglong2 u0 = __ldg((const ulonglong2*)(Ug + (size_t)(k  )*HH + c0));
        ulonglong2 u1 = __ldg((const ulonglong2*)(Ug + (size_t)(k+1)*HH + c0));
        ulonglong2 u2 = __ldg((const ulonglong2*)(Ug + (size_t)(k+2)*HH + c0));
        ulonglong2 u3 = __ldg((const ulonglong2*)(Ug + (size_t)(k+3)*HH + c0));
        #pragma unroll
        for (int i = 0; i < 8; i++) {
            float4 a = *(const float4*)(sA + (m0+i)*HH + k);
            float4 b = *(const float4*)(sB + (m0+i)*HH + k);
            u64 p;
            p = pack2_(a.x); ffma2_(acc01[i], p, w0.x); ffma2_(acc23[i], p, w0.y);
            p = pack2_(a.y); ffma2_(acc01[i], p, w1.x); ffma2_(acc23[i], p, w1.y);
            p = pack2_(a.z); ffma2_(acc01[i], p, w2.x); ffma2_(acc23[i], p, w2.y);
            p = pack2_(a.w); ffma2_(acc01[i], p, w3.x); ffma2_(acc23[i], p, w3.y);
            p = pack2_(b.x); ffma2_(acc01[i], p, u0.x); ffma2_(acc23[i], p, u0.y);
            p = pack2_(b.y); ffma2_(acc01[i], p, u1.x); ffma2_(acc23[i], p, u1.y);
            p = pack2_(b.z); ffma2_(acc01[i], p, u2.x); ffma2_(acc23[i], p, u2.y);
            p = pack2_(b.w); ffma2_(acc01[i], p, u3.x); ffma2_(acc23[i], p, u3.y);
        }
    }
}

// 8-row x 4-col single-panel accumulate
__device__ __forceinline__ void single_acc8(
    const float* __restrict__ Wg, const float* sA,
    int m0, int c0, u64* acc01, u64* acc23)
{
    #pragma unroll 1
    for (int k = 0; k < HH; k += 4) {
        ulonglong2 w0 = __ldg((const ulonglong2*)(Wg + (size_t)(k  )*HH + c0));
        ulonglong2 w1 = __ldg((const ulonglong2*)(Wg + (size_t)(k+1)*HH + c0));
        ulonglong2 w2 = __ldg((const ulonglong2*)(Wg + (size_t)(k+2)*HH + c0));
        ulonglong2 w3 = __ldg((const ulonglong2*)(Wg + (size_t)(k+3)*HH + c0));
        #pragma unroll
        for (int i = 0; i < 8; i++) {
            float4 a = *(const float4*)(sA + (m0+i)*HH + k);
            u64 p;
            p = pack2_(a.x); ffma2_(acc01[i], p, w0.x); ffma2_(acc23[i], p, w0.y);
            p = pack2_(a.y); ffma2_(acc01[i], p, w1.x); ffma2_(acc23[i], p, w1.y);
            p = pack2_(a.z); ffma2_(acc01[i], p, w2.x); ffma2_(acc23[i], p, w2.y);
            p = pack2_(a.w); ffma2_(acc01[i], p, w3.x); ffma2_(acc23[i], p, w3.y);
        }
    }
}

// ---------------- K1: h = relu(x@W_emb + b) + pos ; also init s -------------
__global__ void __launch_bounds__(256, 2) k_embed(
    const float* __restrict__ x, const float* __restrict__ W,
    const float* __restrict__ bias, const float* __restrict__ pos)
{
    extern __shared__ float sm[];
    float* Xs = sm;             // [64][64]
    float* Ws = sm + 64*FF;     // [64][128]
    int tid = threadIdx.x;
    int row0 = blockIdx.x * 64;

    {   // tile loads (contiguous)
        const float4* xg = (const float4*)(x + (size_t)row0*FF);
        float4* Xs4 = (float4*)Xs;
        #pragma unroll
        for (int i = tid; i < 64*FF/4; i += 256) Xs4[i] = xg[i];
        const float4* wg = (const float4*)W;
        float4* Ws4 = (float4*)Ws;
        #pragma unroll
        for (int i = tid; i < FF*HH/4; i += 256) Ws4[i] = wg[i];
    }
    if (tid < 64) {  // init spatial variable s
        int r = row0 + tid;
        int n = r & (NN-1);
        g_s[r*3+0] = ((float)n - (NN-1)*0.5f) / (float)NN;
        g_s[r*3+1] = 0.f;
        g_s[r*3+2] = 0.f;
    }
    __syncthreads();

    int tx = tid & 31, ty = tid >> 5;
    int c0 = tx*4, m0 = ty*8;
    u64 acc01[8], acc23[8];
    #pragma unroll
    for (int i=0;i<8;i++){ acc01[i]=0ull; acc23[i]=0ull; }

    #pragma unroll 2
    for (int k = 0; k < FF; k += 2) {
        ulonglong2 w0 = *(const ulonglong2*)(Ws + (k  )*HH + c0);
        ulonglong2 w1 = *(const ulonglong2*)(Ws + (k+1)*HH + c0);
        #pragma unroll
        for (int i=0;i<8;i++) {
            float2 a = *(const float2*)(Xs + (m0+i)*FF + k);
            u64 a0 = pack2_(a.x), a1 = pack2_(a.y);
            ffma2_(acc01[i], a0, w0.x); ffma2_(acc23[i], a0, w0.y);
            ffma2_(acc01[i], a1, w1.x); ffma2_(acc23[i], a1, w1.y);
        }
    }
    float4 bb = *(const float4*)(bias + c0);
    #pragma unroll
    for (int i=0;i<8;i++) {
        int r = row0 + m0 + i;
        int n = r & (NN-1);
        float4 p = *(const float4*)(pos + (size_t)n*HH + c0);
        float2 v01 = unpack2_(acc01[i]);
        float2 v23 = unpack2_(acc23[i]);
        float4 o;
        o.x = fmaxf(v01.x+bb.x, 0.f) + p.x;
        o.y = fmaxf(v01.y+bb.y, 0.f) + p.y;
        o.z = fmaxf(v23.x+bb.z, 0.f) + p.z;
        o.w = fmaxf(v23.y+bb.w, 0.f) + p.w;
        *(float4*)(g_h + (size_t)r*HH + c0) = o;
    }
}

// ---------------- K2: m = relu(h @ Wm[i] + bm[i])  (64-row tiles) -----------
__global__ void __launch_bounds__(256, 3) k_msg(
    const float* __restrict__ Wm, const float* __restrict__ bm, int iter)
{
    __shared__ float Hs[64*HH];        // 32 KB
    const float* W  = Wm + (size_t)iter*HH*HH;
    const float* bv = bm + (size_t)iter*HH;
    int tid = threadIdx.x;
    int row0 = blockIdx.x * 64;

    {
        const float4* hg = (const float4*)(g_h + (size_t)row0*HH);
        float4* Hs4 = (float4*)Hs;
        #pragma unroll
        for (int i = tid; i < 64*HH/4; i += 256) Hs4[i] = hg[i];
    }
    __syncthreads();

    int tx = tid & 31, ty = tid >> 5;
    int c0 = tx*4, m0 = ty*8;
    u64 acc01[8], acc23[8];
    #pragma unroll
    for (int i=0;i<8;i++){ acc01[i]=0ull; acc23[i]=0ull; }

    single_acc8(W, Hs, m0, c0, acc01, acc23);

    float4 bb = __ldg((const float4*)(bv + c0));
    #pragma unroll
    for (int i=0;i<8;i++) {
        int r = row0 + m0 + i;
        float2 v01 = unpack2_(acc01[i]);
        float2 v23 = unpack2_(acc23[i]);
        float4 o;
        o.x = fmaxf(v01.x+bb.x, 0.f);
        o.y = fmaxf(v01.y+bb.y, 0.f);
        o.z = fmaxf(v23.x+bb.z, 0.f);
        o.w = fmaxf(v23.y+bb.w, 0.f);
        *(float4*)(g_m + (size_t)r*HH + c0) = o;
    }
}

// ---------------- K3: agg = A(s) @ m   (A computed on the fly) --------------
__global__ void __launch_bounds__(256, 2) k_agg(const float* __restrict__ mask)
{
    extern __shared__ float sm[];
    float* s0 = sm;
    float* s1 = sm + 512;
    float* s2 = sm + 1024;
    float* sq = sm + 1536;
    float* As = sm + 2048;              // [64][64]
    float* Ms = sm + 2048 + 64*64;      // [64][128]
    int tid = threadIdx.x;
    int b = blockIdx.x >> 3;
    int itile = blockIdx.x & 7;
    int i0 = itile * 64;                // local row start inside batch

    for (int j = tid; j < NN; j += 256) {
        float a0 = g_s[((size_t)b*NN + j)*3 + 0];
        float a1 = g_s[((size_t)b*NN + j)*3 + 1];
        float a2 = g_s[((size_t)b*NN + j)*3 + 2];
        s0[j]=a0; s1[j]=a1; s2[j]=a2;
        sq[j] = a0*a0 + a1*a1 + a2*a2;
    }
    __syncthreads();

    int tx = tid & 31, ty = tid >> 5;
    int c0 = tx*4, m0 = ty*8;
    u64 acc01[8], acc23[8];
    #pragma unroll
    for (int i=0;i<8;i++){ acc01[i]=0ull; acc23[i]=0ull; }

    const float* maskb = mask + (size_t)b*NN*NN;

    for (int jt = 0; jt < 8; jt++) {
        int j0 = jt * 64;
        // stage m tile
        {
            const float4* mg = (const float4*)(g_m + ((size_t)b*NN + j0)*HH);
            float4* Ms4 = (float4*)Ms;
            #pragma unroll
            for (int i2 = tid; i2 < 64*HH/4; i2 += 256) Ms4[i2] = mg[i2];
        }
        // compute A tile (mask reads coalesced over j)
        #pragma unroll
        for (int p = tid; p < 64*64; p += 256) {
            int jl = p & 63, il = p >> 6;
            int gi = i0 + il, gj = j0 + jl;
            float d2 = sq[gi] + sq[gj]
                     - 2.f*(s0[gi]*s0[gj] + s1[gi]*s1[gj] + s2[gi]*s2[gj]);
            float mv = __ldg(maskb + (size_t)gi*NN + gj);
            As[il*64 + jl] = __expf(-d2*INV_T) * mv;
        }
        __syncthreads();
        #pragma unroll 2
        for (int k = 0; k < 64; k += 2) {
            ulonglong2 w0 = *(const ulonglong2*)(Ms + (k  )*HH + c0);
            ulonglong2 w1 = *(const ulonglong2*)(Ms + (k+1)*HH + c0);
            #pragma unroll
            for (int i=0;i<8;i++) {
                float2 a = *(const float2*)(As + (m0+i)*64 + k);
                u64 a0 = pack2_(a.x), a1 = pack2_(a.y);
                ffma2_(acc01[i], a0, w0.x); ffma2_(acc23[i], a0, w0.y);
                ffma2_(acc01[i], a1, w1.x); ffma2_(acc23[i], a1, w1.y);
            }
        }
        __syncthreads();
    }
    int rbase = b*NN + i0;
    #pragma unroll
    for (int i=0;i<8;i++) {
        float2 v01 = unpack2_(acc01[i]);
        float2 v23 = unpack2_(acc23[i]);
        float4 o; o.x=v01.x; o.y=v01.y; o.z=v23.x; o.w=v23.y;
        *(float4*)(g_agg + (size_t)(rbase+m0+i)*HH + c0) = o;
    }
}

// -------- K4: fused GRU vertex update + positional GRU (64-row tiles) -------
// Panel order r -> hh -> z keeps gates transient; rh smem carries r*h, then
// tanh(hh), then h_new (all thread-private column writes within warp rows).
__global__ void __launch_bounds__(256, 2) k_gru(
    const float* __restrict__ Wz_, const float* __restrict__ Uz_, const float* __restrict__ bz_,
    const float* __restrict__ Wr_, const float* __restrict__ Ur_, const float* __restrict__ br_,
    const float* __restrict__ Wh_, const float* __restrict__ Uh_, const float* __restrict__ bh_,
    const float* __restrict__ Wpz, const float* __restrict__ Upz, const float* __restrict__ bpz,
    const float* __restrict__ Wpr, const float* __restrict__ Upr, const float* __restrict__ bpr,
    const float* __restrict__ Wph, const float* __restrict__ Uph, const float* __restrict__ bph,
    int iter)
{
    extern __shared__ float smg[];
    float* aggs = smg;              // [64][128] 32 KB
    float* hs   = smg + 64*HH;      // [64][128] 32 KB
    float* rh   = smg + 2*64*HH;    // [64][128] 32 KB: r*h -> tanh -> h_new
    float* srs  = smg + 3*64*HH;    // [64*3]

    const float* Wz = Wz_ + (size_t)iter*HH*HH;
    const float* Uz = Uz_ + (size_t)iter*HH*HH;
    const float* Wr = Wr_ + (size_t)iter*HH*HH;
    const float* Ur = Ur_ + (size_t)iter*HH*HH;
    const float* Wh = Wh_ + (size_t)iter*HH*HH;
    const float* Uh = Uh_ + (size_t)iter*HH*HH;
    const float* bz = bz_ + (size_t)iter*HH;
    const float* br = br_ + (size_t)iter*HH;
    const float* bh = bh_ + (size_t)iter*HH;

    int tid = threadIdx.x;
    int row0 = blockIdx.x * 64;

    {
        const float4* ag = (const float4*)(g_agg + (size_t)row0*HH);
        const float4* hg = (const float4*)(g_h  + (size_t)row0*HH);
        float4* a4 = (float4*)aggs; float4* h4 = (float4*)hs;
        #pragma unroll
        for (int i = tid; i < 64*HH/4; i += 256) { a4[i] = ag[i]; h4[i] = hg[i]; }
    }
    __syncthreads();

    int tx = tid & 31, ty = tid >> 5;
    int c0 = tx*4, m0 = ty*8;

    // ---- r panel: rh = sig(aggs@Wr + hs@Ur + br) * hs ----------------------
    {
        u64 acc01[8], acc23[8];
        #pragma unroll
        for (int i=0;i<8;i++){ acc01[i]=0ull; acc23[i]=0ull; }
        dual_acc8(Wr, Ur, aggs, hs, m0, c0, acc01, acc23);
        float4 bb = __ldg((const float4*)(br + c0));
        #pragma unroll
        for (int i=0;i<8;i++) {
            float2 v01 = unpack2_(acc01[i]);
            float2 v23 = unpack2_(acc23[i]);
            float rr[4] = { sig_(v01.x+bb.x), sig_(v01.y+bb.y),
                            sig_(v23.x+bb.z), sig_(v23.y+bb.w) };
            #pragma unroll
            for (int j=0;j<4;j++)
                rh[(m0+i)*HH + c0 + j] = rr[j] * hs[(m0+i)*HH + c0 + j];
        }
    }
    __syncwarp();   // warp rows m0..m0+7 of rh complete for this warp

    // ---- hh panel: rh <- tanh(aggs@Wh + rh@Uh + bh)  -----------------------
    {
        u64 acc01[8], acc23[8];
        #pragma unroll
        for (int i=0;i<8;i++){ acc01[i]=0ull; acc23[i]=0ull; }
        dual_acc8(Wh, Uh, aggs, rh, m0, c0, acc01, acc23);
        float4 bb = __ldg((const float4*)(bh + c0));
        float th[8][4];
        #pragma unroll
        for (int i=0;i<8;i++) {
            float2 v01 = unpack2_(acc01[i]);
            float2 v23 = unpack2_(acc23[i]);
            th[i][0]=tanh_(v01.x+bb.x); th[i][1]=tanh_(v01.y+bb.y);
            th[i][2]=tanh_(v23.x+bb.z); th[i][3]=tanh_(v23.y+bb.w);
        }
        __syncwarp();           // warp done reading rh (r*h) rows
        #pragma unroll
        for (int i=0;i<8;i++) {
            float4 o; o.x=th[i][0]; o.y=th[i][1]; o.z=th[i][2]; o.w=th[i][3];
            *(float4*)(rh + (m0+i)*HH + c0) = o;
        }
    }
    // no sync needed: z panel reads only aggs/hs; rh re-read is thread-private

    // ---- z panel + h update: h_new -> g_h and rh ---------------------------
    {
        u64 acc01[8], acc23[8];
        #pragma unroll
        for (int i=0;i<8;i++){ acc01[i]=0ull; acc23[i]=0ull; }
        dual_acc8(Wz, Uz, aggs, hs, m0, c0, acc01, acc23);
        float4 bb = __ldg((const float4*)(bz + c0));
        #pragma unroll
        for (int i=0;i<8;i++) {
            float2 v01 = unpack2_(acc01[i]);
            float2 v23 = unpack2_(acc23[i]);
            float zv[4] = { sig_(v01.x+bb.x), sig_(v01.y+bb.y),
                            sig_(v23.x+bb.z), sig_(v23.y+bb.w) };
            float hn[4];
            #pragma unroll
            for (int j=0;j<4;j++) {
                float hv = hs[(m0+i)*HH + c0 + j];
                float tv = rh[(m0+i)*HH + c0 + j];   // own thread's tanh value
                hn[j] = (1.f - zv[j])*hv + zv[j]*tv;
                rh[(m0+i)*HH + c0 + j] = hn[j];       // thread-private overwrite
            }
            float4 o; o.x=hn[0]; o.y=hn[1]; o.z=hn[2]; o.w=hn[3];
            *(float4*)(g_h + (size_t)(row0+m0+i)*HH + c0) = o;
        }
    }
    __syncthreads();

    // ---- positional GRU (3-dim state), 3 threads per row; h_new in rh ------
    int m = tid / 3, d = tid - m*3;
    int r = row0 + m;
    float sv0=0.f, sv1=0.f, sv2=0.f, ah=0.f, zs=0.f;
    if (tid < 192) {
        sv0 = g_s[(size_t)r*3+0]; sv1 = g_s[(size_t)r*3+1]; sv2 = g_s[(size_t)r*3+2];
        float az=0.f, ar=0.f; ah=0.f;
        #pragma unroll 4
        for (int k = 0; k < HH; k++) {
            float hv = rh[m*HH + k];
            az += hv * __ldg(Wpz + k*3 + d);
            ar += hv * __ldg(Wpr + k*3 + d);
            ah += hv * __ldg(Wph + k*3 + d);
        }
        float zu = sv0*__ldg(Upz+0+d) + sv1*__ldg(Upz+3+d) + sv2*__ldg(Upz+6+d);
        float ru = sv0*__ldg(Upr+0+d) + sv1*__ldg(Upr+3+d) + sv2*__ldg(Upr+6+d);
        zs = sig_(az + zu + __ldg(bpz + d));
        float rsv = sig_(ar + ru + __ldg(bpr + d));
        srs[m*3 + d] = rsv;
    }
    __syncthreads();
    if (tid < 192) {
        float hu = srs[m*3+0]*sv0*__ldg(Uph+0+d)
                 + srs[m*3+1]*sv1*__ldg(Uph+3+d)
                 + srs[m*3+2]*sv2*__ldg(Uph+6+d);
        float ssv = tanh_(ah + hu + __ldg(bph + d));
        float sd = (d==0) ? sv0 : (d==1) ? sv1 : sv2;
        g_s[(size_t)r*3 + d] = (1.f - zs)*sd + zs*ssv;
    }
}

// ---------------- K5: final A = exp(-d2/T) * mask ---------------------------
__global__ void k_final(const float* __restrict__ mask, float* __restrict__ out)
{
    __shared__ float s0[512], s1[512], s2[512], sq[512];
    int tid = threadIdx.x;
    int b = blockIdx.x >> 3;
    int itile = blockIdx.x & 7;
    int i0 = itile * 64;

    for (int j = tid; j < NN; j += 256) {
        float a0 = g_s[((size_t)b*NN + j)*3 + 0];
        float a1 = g_s[((size_t)b*NN + j)*3 + 1];
        float a2 = g_s[((size_t)b*NN + j)*3 + 2];
        s0[j]=a0; s1[j]=a1; s2[j]=a2;
        sq[j] = a0*a0 + a1*a1 + a2*a2;
    }
    __syncthreads();

    const float* maskb = mask + (size_t)b*NN*NN;
    float* outb = out + (size_t)b*NN*NN;
    #pragma unroll 4
    for (int p = tid; p < 64*NN; p += 256) {
        int j  = p & (NN-1);
        int il = p >> 9;
        int gi = i0 + il;
        float d2 = sq[gi] + sq[j]
                 - 2.f*(s0[gi]*s0[j] + s1[gi]*s1[j] + s2[gi]*s2[j]);
        outb[(size_t)gi*NN + j] = __expf(-d2*INV_T) * __ldg(maskb + (size_t)gi*NN + j);
    }
}

// ---------------- launch -----------------------------------------------------
extern "C" void kernel_launch(void* const* d_in, const int* in_sizes, int n_in,
                              void* d_out, int out_size)
{
    (void)in_sizes; (void)n_in; (void)out_size;
    const float* x     = (const float*)d_in[0];
    const float* mask  = (const float*)d_in[1];
    const float* W_emb = (const float*)d_in[2];
    const float* b_emb = (const float*)d_in[3];
    const float* pos   = (const float*)d_in[4];
    const float* Wm    = (const float*)d_in[5];
    const float* bm    = (const float*)d_in[6];
    const float* Wz    = (const float*)d_in[7];
    const float* Uz    = (const float*)d_in[8];
    const float* bz    = (const float*)d_in[9];
    const float* Wr    = (const float*)d_in[10];
    const float* Ur    = (const float*)d_in[11];
    const float* br    = (const float*)d_in[12];
    const float* Wh    = (const float*)d_in[13];
    const float* Uh    = (const float*)d_in[14];
    const float* bh    = (const float*)d_in[15];
    const float* Wpz   = (const float*)d_in[16];
    const float* Upz   = (const float*)d_in[17];
    const float* bpz   = (const float*)d_in[18];
    const float* Wpr   = (const float*)d_in[19];
    const float* Upr   = (const float*)d_in[20];
    const float* bpr   = (const float*)d_in[21];
    const float* Wph   = (const float*)d_in[22];
    const float* Uph   = (const float*)d_in[23];
    const float* bph   = (const float*)d_in[24];
    float* out = (float*)d_out;

    const int smem_embed = (64*FF + FF*HH) * 4;                  // 48 KB
    const int smem_agg   = (4*512 + 64*64 + 64*HH) * 4;          // 56 KB
    const int smem_gru   = (3*64*HH + 64*3) * 4;                 // ~96.8 KB

    cudaFuncSetAttribute(k_embed, cudaFuncAttributeMaxDynamicSharedMemorySize, smem_embed);
    cudaFuncSetAttribute(k_agg,   cudaFuncAttributeMaxDynamicSharedMemorySize, smem_agg);
    cudaFuncSetAttribute(k_gru,   cudaFuncAttributeMaxDynamicSharedMemorySize, smem_gru);

    k_embed<<<RR/64, 256, smem_embed>>>(x, W_emb, b_emb, pos);
    for (int it = 0; it < 3; it++) {
        k_msg<<<RR/64, 256>>>(Wm, bm, it);
        k_agg<<<BB*8, 256, smem_agg>>>(mask);
        k_gru<<<RR/64, 256, smem_gru>>>(Wz,Uz,bz, Wr,Ur,br, Wh,Uh,bh,
                                        Wpz,Upz,bpz, Wpr,Upr,bpr, Wph,Uph,bph, it);
    }
    k_final<<<BB*8, 256>>>(mask, out);
}